// round 11
// baseline (speedup 1.0000x reference)
#include <cuda_runtime.h>
#include <cuda_fp16.h>
#include <cstdint>

#define DI __device__ __forceinline__

static constexpr int BB = 64, NN = 256, HH = 1024, OO = 768;
static constexpr int NI = 256;  // nin dim (OO/3)

// ---- static device scratch (no allocs allowed) ----
__device__ __align__(256) __half g_wd[(size_t)3 * BB * NN * NI];  // wd[d][b][n][nin]
__device__ __align__(256) float  g_pre[(size_t)BB * NN * HH];     // pre-LN [b][n][h]

// ---- helpers ----
DI uint32_t s2u(const void* p) {
    uint32_t a;
    asm("{ .reg .u64 t; cvta.to.shared.u64 t, %1; cvt.u32.u64 %0, t; }" : "=r"(a) : "l"(p));
    return a;
}
DI void ldx4(uint32_t r[4], uint32_t addr) {
    asm volatile("ldmatrix.sync.aligned.m8n8.x4.shared.b16 {%0,%1,%2,%3}, [%4];"
        : "=r"(r[0]), "=r"(r[1]), "=r"(r[2]), "=r"(r[3]) : "r"(addr));
}
DI void mma16816(float c[4], const uint32_t a[4], const uint32_t b[2]) {
    asm volatile("mma.sync.aligned.m16n8k16.row.col.f32.f16.f16.f32 "
        "{%0,%1,%2,%3}, {%4,%5,%6,%7}, {%8,%9}, {%0,%1,%2,%3};"
        : "+f"(c[0]), "+f"(c[1]), "+f"(c[2]), "+f"(c[3])
        : "r"(a[0]), "r"(a[1]), "r"(a[2]), "r"(a[3]), "r"(b[0]), "r"(b[1]));
}
DI uint32_t pkh(__half a, __half b) {
    return (uint32_t)__half_as_ushort(a) | ((uint32_t)__half_as_ushort(b) << 16);
}

// smem stage: A(16K) B(16K) = 32KB/stage, 2 stages = 64KB.
// Epilogue transpose reuses smem: 128*129*4 = 66048 -> SMEM_TOTAL.
static constexpr int STG = 32768;
static constexpr int SMEM_TOTAL = 66048;

// fp32 128x64 tile -> fp16, swizzled store
DI void load_f32_hi(const float* __restrict__ g, int lda, char* H, int tid) {
#pragma unroll
    for (int i = 0; i < 4; i++) {
        int q = tid + 256 * i, row = q >> 3, ck = q & 7;
        const float* p = g + (size_t)row * lda + ck * 8;
        float4 v0 = *(const float4*)p;
        float4 v1 = *(const float4*)(p + 4);
        float fv[8] = {v0.x, v0.y, v0.z, v0.w, v1.x, v1.y, v1.z, v1.w};
        uint32_t hp[4];
#pragma unroll
        for (int j = 0; j < 4; j++)
            hp[j] = pkh(__float2half_rn(fv[2 * j]), __float2half_rn(fv[2 * j + 1]));
        int off = row * 128 + ((ck ^ (row & 7)) << 4);
        *(uint4*)(H + off) = make_uint4(hp[0], hp[1], hp[2], hp[3]);
    }
}

// fp16 128x64 tile -> swizzled copy
DI void load_h16(const __half* __restrict__ g, int lda, char* D, int tid) {
#pragma unroll
    for (int i = 0; i < 4; i++) {
        int q = tid + 256 * i, row = q >> 3, ck = q & 7;
        int off = row * 128 + ((ck ^ (row & 7)) << 4);
        *(uint4*)(D + off) = *(const uint4*)(g + (size_t)row * lda + ck * 8);
    }
}

// Shifted-k A tile: A[r][ninc] = fp16(k[b][nin0+ninc][h0 + r + dh]), zero-padded.
// kcol = k + (b*NN + nin0)*HH. Thread: ninc = tid&63, hs = (tid>>6)*32.
DI void load_kshift(const float* __restrict__ kcol, int h0, int dh, char* A, int tid) {
    const int ninc = tid & 63, hs = (tid >> 6) << 5;
    const float* p = kcol + (size_t)ninc * HH + h0 + hs;
    const uint32_t cbase = (uint32_t)((ninc & 7) * 2);
    const uint32_t cchunk = (uint32_t)(ninc >> 3);
#pragma unroll
    for (int q = 0; q < 8; q++) {
        float4 v = *(const float4*)(p + q * 4);
        float vv[4] = {v.x, v.y, v.z, v.w};
#pragma unroll
        for (int e = 0; e < 4; e++) {
            int r = hs + q * 4 + e - dh;
            if (r >= 0 && r < 128) {
                uint32_t off = (uint32_t)r * 128 + (((cchunk ^ (uint32_t)(r & 7)) << 4) | cbase);
                *(__half*)(A + off) = __float2half_rn(vv[e]);
            }
        }
    }
    if (dh == -1 && hs == 0) {        // row 0 <- k[h0-1]
        float v = (h0 > 0) ? p[-1] : 0.f;
        uint32_t off = ((cchunk ^ 0u) << 4) | cbase;
        *(__half*)(A + off) = __float2half_rn(v);
    }
    if (dh == 1 && hs == 96) {        // row 127 <- k[h0+128]
        float v = (h0 + 128 < HH) ? p[32] : 0.f;
        uint32_t off = 127u * 128 + (((cchunk ^ 7u) << 4) | cbase);
        *(__half*)(A + off) = __float2half_rn(v);
    }
}

// One 64-wide K stage: acc += A.B
DI void compute_stage1(uint32_t smb, int buf, int wr, int wc, int lane, float acc[4][4][4]) {
    uint32_t Ah = smb + buf * STG;
    uint32_t Bh = Ah + 16384;
    const int ar = wr * 64 + (lane & 15);
    const int br = wc * 32 + (lane & 7) + ((lane & 16) >> 1);
    const int ax = lane & 7;
#pragma unroll
    for (int kk = 0; kk < 4; kk++) {
        const int ac = kk * 2 + (lane >> 4);
        const int bc = kk * 2 + ((lane >> 3) & 1);
        uint32_t ah[4][4], bh[4][2];
#pragma unroll
        for (int mt = 0; mt < 4; mt++)
            ldx4(ah[mt], Ah + (uint32_t)(ar + mt * 16) * 128 + (uint32_t)((ac ^ ax) << 4));
#pragma unroll
        for (int p = 0; p < 2; p++) {
            uint32_t off = (uint32_t)(br + p * 16) * 128 + (uint32_t)((bc ^ ax) << 4);
            uint32_t q[4];
            ldx4(q, Bh + off);
            bh[2 * p][0] = q[0]; bh[2 * p][1] = q[1];
            bh[2 * p + 1][0] = q[2]; bh[2 * p + 1][1] = q[3];
        }
#pragma unroll
        for (int mt = 0; mt < 4; mt++)
#pragma unroll
            for (int nt = 0; nt < 4; nt++) mma16816(acc[mt][nt], ah[mt], bh[nt]);
    }
}

// acc -> padded smem transpose
DI void epilogue_to_smem(float* eps, int wr, int wc, int lane, float acc[4][4][4]) {
#pragma unroll
    for (int mt = 0; mt < 4; mt++)
#pragma unroll
        for (int nt = 0; nt < 4; nt++) {
            int m = wr * 64 + mt * 16 + (lane >> 2);
            int n = wc * 32 + nt * 8 + (lane & 3) * 2;
            eps[m * 129 + n]           = acc[mt][nt][0];
            eps[m * 129 + n + 1]       = acc[mt][nt][1];
            eps[(m + 8) * 129 + n]     = acc[mt][nt][2];
            eps[(m + 8) * 129 + n + 1] = acc[mt][nt][3];
        }
}

// ===== GEMM1: wd[o%3][b][n][o/3] = f[b,n,:].W_lin[o,:] + b_lin[o] =====
__global__ void __launch_bounds__(256, 2)
gemm1_kernel(const float* __restrict__ W, const float* __restrict__ f,
             const float* __restrict__ bias) {
    extern __shared__ char sm[];
    uint32_t smb = s2u(sm);
    const int m0 = blockIdx.x * 128, n0 = blockIdx.y * 128, b = blockIdx.z;
    const int tid = threadIdx.x, w = tid >> 5, lane = tid & 31;
    const int wr = w >> 2, wc = w & 3;
    const float* Abase = W + (size_t)m0 * HH;
    const float* Bbase = f + ((size_t)b * NN + n0) * HH;

    float acc[4][4][4];
#pragma unroll
    for (int i = 0; i < 4; i++)
#pragma unroll
        for (int j = 0; j < 4; j++)
#pragma unroll
            for (int c = 0; c < 4; c++) acc[i][j][c] = 0.f;

    load_f32_hi(Abase, HH, sm, tid);
    load_f32_hi(Bbase, HH, sm + 16384, tid);
    __syncthreads();

    const int NS = HH / 64;  // 16
    for (int s = 0; s < NS; s++) {
        if (s + 1 < NS) {
            char* nb = sm + ((s + 1) & 1) * STG;
            load_f32_hi(Abase + (s + 1) * 64, HH, nb, tid);
            load_f32_hi(Bbase + (s + 1) * 64, HH, nb + 16384, tid);
        }
        compute_stage1(smb, s & 1, wr, wc, lane, acc);
        __syncthreads();
    }

    float* eps = (float*)sm;
    epilogue_to_smem(eps, wr, wc, lane, acc);
    __syncthreads();

    const int m = tid & 127, nh = (tid >> 7) * 64;
    const int o = m0 + m, d = o % 3, nin = o / 3;
    const float bv = bias[o];
    __half* oh = g_wd + (((size_t)d * BB + b) * NN + n0) * NI + nin;
#pragma unroll 8
    for (int j = 0; j < 64; j++) {
        int n = nh + j;
        oh[(size_t)n * NI] = __float2half_rn(eps[m * 129 + n] + bv);
    }
}

// ===== GEMM2: pre[b][n][h] = sum_d sum_nin k[b][nin][h+d-1] * wd[d][b][n][nin] =====
__global__ void __launch_bounds__(256, 2)
gemm2_kernel(const float* __restrict__ k) {
    extern __shared__ char sm[];
    uint32_t smb = s2u(sm);
    const int m0 = blockIdx.x * 128, n0 = blockIdx.y * 128, b = blockIdx.z;  // m0 = h0
    const int tid = threadIdx.x, w = tid >> 5, lane = tid & 31;
    const int wr = w >> 2, wc = w & 3;

    float acc[4][4][4];
#pragma unroll
    for (int i = 0; i < 4; i++)
#pragma unroll
        for (int j = 0; j < 4; j++)
#pragma unroll
            for (int c = 0; c < 4; c++) acc[i][j][c] = 0.f;

    const int NS = 12;  // 3 d-terms x 4 nin-chunks of 64
    // stage s: d = s>>2, dh = d-1, nin0 = (s&3)*64
    {
        const float* kcol = k + (size_t)b * NN * HH;  // s=0: nin0=0
        load_kshift(kcol, m0, -1, sm, tid);
        load_h16(g_wd + ((size_t)b * NN + n0) * NI, NI, sm + 16384, tid);
    }
    __syncthreads();

    for (int s = 0; s < NS; s++) {
        if (s + 1 < NS) {
            int sn = s + 1, dn = sn >> 2, nin0n = (sn & 3) * 64;
            char* nb = sm + (sn & 1) * STG;
            const float* kcol = k + ((size_t)b * NN + nin0n) * HH;
            load_kshift(kcol, m0, dn - 1, nb, tid);
            load_h16(g_wd + (((size_t)dn * BB + b) * NN + n0) * NI + nin0n, NI, nb + 16384, tid);
        }
        compute_stage1(smb, s & 1, wr, wc, lane, acc);
        __syncthreads();
    }

    float* eps = (float*)sm;
    epilogue_to_smem(eps, wr, wc, lane, acc);
    __syncthreads();

    const int m = tid & 127, nh = (tid >> 7) * 64;
    float* ob = g_pre + ((size_t)b * NN + n0) * HH + m0 + m;
#pragma unroll 8
    for (int j = 0; j < 64; j++) {
        int n = nh + j;
        ob[(size_t)n * HH] = eps[m * 129 + n];
    }
}

// LayerNorm over H per (b,n) row
__global__ void __launch_bounds__(256)
ln_kernel(const float* __restrict__ gamma, const float* __restrict__ beta,
          float* __restrict__ out) {
    const int row = blockIdx.x, tid = threadIdx.x;
    const float* x = g_pre + (size_t)row * HH;
    float4 v = *(const float4*)(x + tid * 4);
    float s = v.x + v.y + v.z + v.w;
    float q = v.x * v.x + v.y * v.y + v.z * v.z + v.w * v.w;
#pragma unroll
    for (int o = 16; o; o >>= 1) {
        s += __shfl_xor_sync(0xFFFFFFFFu, s, o);
        q += __shfl_xor_sync(0xFFFFFFFFu, q, o);
    }
    __shared__ float ss[8], sq[8], red[2];
    if ((tid & 31) == 0) { ss[tid >> 5] = s; sq[tid >> 5] = q; }
    __syncthreads();
    if (tid == 0) {
        float S = 0.f, Q = 0.f;
#pragma unroll
        for (int i = 0; i < 8; i++) { S += ss[i]; Q += sq[i]; }
        float mu = S * (1.0f / HH);
        float var = Q * (1.0f / HH) - mu * mu;
        red[0] = mu;
        red[1] = rsqrtf(var + 1e-5f);
    }
    __syncthreads();
    const float mu = red[0], rinv = red[1];
    const int h = tid * 4;
    float4 g = *(const float4*)(gamma + h);
    float4 bt = *(const float4*)(beta + h);
    float4 y;
    y.x = (v.x - mu) * rinv * g.x + bt.x;
    y.y = (v.y - mu) * rinv * g.y + bt.y;
    y.z = (v.z - mu) * rinv * g.z + bt.z;
    y.w = (v.w - mu) * rinv * g.w + bt.w;
    *(float4*)(out + (size_t)row * HH + h) = y;
}

extern "C" void kernel_launch(void* const* d_in, const int* in_sizes, int n_in,
                              void* d_out, int out_size) {
    const float* f  = (const float*)d_in[0];
    const float* k  = (const float*)d_in[1];
    const float* W  = (const float*)d_in[2];
    const float* bl = (const float*)d_in[3];
    const float* gm = (const float*)d_in[4];
    const float* bt = (const float*)d_in[5];
    float* out = (float*)d_out;

    cudaFuncSetAttribute(gemm1_kernel, cudaFuncAttributeMaxDynamicSharedMemorySize, SMEM_TOTAL);
    cudaFuncSetAttribute(gemm2_kernel, cudaFuncAttributeMaxDynamicSharedMemorySize, SMEM_TOTAL);

    gemm1_kernel<<<dim3(OO / 128, NN / 128, BB), 256, SMEM_TOTAL>>>(W, f, bl);
    gemm2_kernel<<<dim3(HH / 128, NN / 128, BB), 256, SMEM_TOTAL>>>(k);
    ln_kernel<<<BB * NN, 256>>>(gm, bt, out);
}

// round 14
// speedup vs baseline: 1.5223x; 1.5223x over previous
#include <cuda_runtime.h>
#include <cuda_fp16.h>
#include <cstdint>

#define DI __device__ __forceinline__

static constexpr int BB = 64, NN = 256, HH = 1024, OO = 768;

// ---- static device scratch (no allocs allowed) ----
__device__ __align__(256) __half g_f16[(size_t)BB * NN * HH];    // fp16(f)
__device__ __align__(256) __half g_W16[(size_t)OO * HH];         // fp16(W_lin)
__device__ __align__(256) __half g_kt[(size_t)BB * HH * OO];     // kt [b][h][o]
__device__ __align__(256) __half g_w[(size_t)BB * NN * OO];      // weight [b][n][o]
__device__ __align__(256) float  g_pre[(size_t)BB * NN * HH];    // pre-LN [b][n][h]

// ---- helpers ----
DI uint32_t s2u(const void* p) {
    uint32_t a;
    asm("{ .reg .u64 t; cvta.to.shared.u64 t, %1; cvt.u32.u64 %0, t; }" : "=r"(a) : "l"(p));
    return a;
}
DI void ldx4(uint32_t r[4], uint32_t addr) {
    asm volatile("ldmatrix.sync.aligned.m8n8.x4.shared.b16 {%0,%1,%2,%3}, [%4];"
        : "=r"(r[0]), "=r"(r[1]), "=r"(r[2]), "=r"(r[3]) : "r"(addr));
}
DI void mma16816(float c[4], const uint32_t a[4], const uint32_t b[2]) {
    asm volatile("mma.sync.aligned.m16n8k16.row.col.f32.f16.f16.f32 "
        "{%0,%1,%2,%3}, {%4,%5,%6,%7}, {%8,%9}, {%0,%1,%2,%3};"
        : "+f"(c[0]), "+f"(c[1]), "+f"(c[2]), "+f"(c[3])
        : "r"(a[0]), "r"(a[1]), "r"(a[2]), "r"(a[3]), "r"(b[0]), "r"(b[1]));
}

// 2 stages x (A 16K + B 16K) = 64KB; epilogue transpose needs 66048 -> SMEM_TOTAL.
static constexpr int STG = 32768;
static constexpr int SMEM_TOTAL = 66048;

// LDG a fp16 128x64 tile into 4 uint4 regs (per-thread lines)
DI void ldg_tile(uint4 r[4], const __half* __restrict__ g, int lda, int tid) {
#pragma unroll
    for (int i = 0; i < 4; i++) {
        int q = tid + 256 * i, row = q >> 3, ck = q & 7;
        r[i] = *(const uint4*)(g + (size_t)row * lda + ck * 8);
    }
}
// STS those regs into swizzled smem tile
DI void sts_tile(const uint4 r[4], char* D, int tid) {
#pragma unroll
    for (int i = 0; i < 4; i++) {
        int q = tid + 256 * i, row = q >> 3, ck = q & 7;
        int off = row * 128 + ((ck ^ (row & 7)) << 4);
        *(uint4*)(D + off) = r[i];
    }
}

// One 64-wide K stage: acc += A.B
DI void compute_stage1(uint32_t smb, int buf, int wr, int wc, int lane, float acc[4][4][4]) {
    uint32_t Ah = smb + buf * STG;
    uint32_t Bh = Ah + 16384;
    const int ar = wr * 64 + (lane & 15);
    const int br = wc * 32 + (lane & 7) + ((lane & 16) >> 1);
    const int ax = lane & 7;
#pragma unroll
    for (int kk = 0; kk < 4; kk++) {
        const int ac = kk * 2 + (lane >> 4);
        const int bc = kk * 2 + ((lane >> 3) & 1);
        uint32_t ah[4][4], bh[4][2];
#pragma unroll
        for (int mt = 0; mt < 4; mt++)
            ldx4(ah[mt], Ah + (uint32_t)(ar + mt * 16) * 128 + (uint32_t)((ac ^ ax) << 4));
#pragma unroll
        for (int p = 0; p < 2; p++) {
            uint32_t off = (uint32_t)(br + p * 16) * 128 + (uint32_t)((bc ^ ax) << 4);
            uint32_t q[4];
            ldx4(q, Bh + off);
            bh[2 * p][0] = q[0]; bh[2 * p][1] = q[1];
            bh[2 * p + 1][0] = q[2]; bh[2 * p + 1][1] = q[3];
        }
#pragma unroll
        for (int mt = 0; mt < 4; mt++)
#pragma unroll
            for (int nt = 0; nt < 4; nt++) mma16816(acc[mt][nt], ah[mt], bh[nt]);
    }
}

// acc -> padded smem transpose
DI void epilogue_to_smem(float* eps, int wr, int wc, int lane, float acc[4][4][4]) {
#pragma unroll
    for (int mt = 0; mt < 4; mt++)
#pragma unroll
        for (int nt = 0; nt < 4; nt++) {
            int m = wr * 64 + mt * 16 + (lane >> 2);
            int n = wc * 32 + nt * 8 + (lane & 3) * 2;
            eps[m * 129 + n]           = acc[mt][nt][0];
            eps[m * 129 + n + 1]       = acc[mt][nt][1];
            eps[(m + 8) * 129 + n]     = acc[mt][nt][2];
            eps[(m + 8) * 129 + n + 1] = acc[mt][nt][3];
        }
}

// generic fp16 GEMM core, register-prefetch double buffer
DI void gemm_core(char* sm, uint32_t smb, const __half* A, int lda, const __half* B, int ldb,
                  int NS, int tid, int wr, int wc, int lane, float acc[4][4][4]) {
    uint4 ra[4], rb[4];
    ldg_tile(ra, A, lda, tid);
    ldg_tile(rb, B, ldb, tid);
    sts_tile(ra, sm, tid);
    sts_tile(rb, sm + 16384, tid);
    __syncthreads();
    for (int s = 0; s < NS; s++) {
        if (s + 1 < NS) {
            ldg_tile(ra, A + (s + 1) * 64, lda, tid);
            ldg_tile(rb, B + (s + 1) * 64, ldb, tid);
        }
        compute_stage1(smb, s & 1, wr, wc, lane, acc);
        if (s + 1 < NS) {
            char* nb = sm + ((s + 1) & 1) * STG;
            sts_tile(ra, nb, tid);
            sts_tile(rb, nb + 16384, tid);
        }
        __syncthreads();
    }
}

// ===== GEMM1: w[b][n][o] = f16[b,n,:].W16[o,:] + b_lin[o] =====
__global__ void __launch_bounds__(256, 2)
gemm1_kernel(const float* __restrict__ bias) {
    extern __shared__ char sm[];
    uint32_t smb = s2u(sm);
    const int m0 = blockIdx.x * 128, n0 = blockIdx.y * 128, b = blockIdx.z;
    const int tid = threadIdx.x, w = tid >> 5, lane = tid & 31;
    const int wr = w >> 2, wc = w & 3;

    float acc[4][4][4];
#pragma unroll
    for (int i = 0; i < 4; i++)
#pragma unroll
        for (int j = 0; j < 4; j++)
#pragma unroll
            for (int c = 0; c < 4; c++) acc[i][j][c] = 0.f;

    gemm_core(sm, smb, g_W16 + (size_t)m0 * HH, HH,
              g_f16 + ((size_t)b * NN + n0) * HH, HH, HH / 64, tid, wr, wc, lane, acc);

    float* eps = (float*)sm;
    epilogue_to_smem(eps, wr, wc, lane, acc);
    __syncthreads();

    const int m = tid & 127, nh = (tid >> 7) * 64;
    const float bv = bias[m0 + m];
    __half* oh = g_w + ((size_t)b * NN + n0) * OO + m0 + m;
#pragma unroll 8
    for (int j = 0; j < 64; j++) {
        int n = nh + j;
        oh[(size_t)n * OO] = __float2half_rn(eps[m * 129 + n] + bv);
    }
}

// ===== GEMM2: pre[b][n][h] = kt[b,h,:].w[b,n,:] =====
__global__ void __launch_bounds__(256, 2)
gemm2_kernel() {
    extern __shared__ char sm[];
    uint32_t smb = s2u(sm);
    const int m0 = blockIdx.x * 128, n0 = blockIdx.y * 128, b = blockIdx.z;
    const int tid = threadIdx.x, w = tid >> 5, lane = tid & 31;
    const int wr = w >> 2, wc = w & 3;

    float acc[4][4][4];
#pragma unroll
    for (int i = 0; i < 4; i++)
#pragma unroll
        for (int j = 0; j < 4; j++)
#pragma unroll
            for (int c = 0; c < 4; c++) acc[i][j][c] = 0.f;

    gemm_core(sm, smb, g_kt + ((size_t)b * HH + m0) * OO, OO,
              g_w + ((size_t)b * NN + n0) * OO, OO, OO / 64, tid, wr, wc, lane, acc);

    float* eps = (float*)sm;
    epilogue_to_smem(eps, wr, wc, lane, acc);
    __syncthreads();

    const int m = tid & 127, nh = (tid >> 7) * 64;
    float* ob = g_pre + ((size_t)b * NN + n0) * HH + m0 + m;
#pragma unroll 8
    for (int j = 0; j < 64; j++) {
        int n = nh + j;
        ob[(size_t)n * HH] = eps[m * 129 + n];
    }
}

// fp32 -> fp16 streaming convert
__global__ void __launch_bounds__(256)
cvt_kernel(const float* __restrict__ src, __half* __restrict__ dst, int n4) {
    int i = blockIdx.x * 256 + threadIdx.x;
    if (i < n4) {
        float4 v = ((const float4*)src)[i];
        ((__half2*)dst)[2 * i]     = __floats2half2_rn(v.x, v.y);
        ((__half2*)dst)[2 * i + 1] = __floats2half2_rn(v.z, v.w);
    }
}

// kt[b][h][o] = fp16( k[b][o/3][h + o%3 - 1] ), zero-padded.
__global__ void __launch_bounds__(256)
ktbuild_kernel(const float* __restrict__ k) {
    __shared__ float sm[64][68];
    const int b = blockIdx.z, nin0 = blockIdx.x * 64, h0 = blockIdx.y * 64;
    const int tid = threadIdx.x;
    for (int idx = tid; idx < 64 * 66; idx += 256) {
        int i = idx / 66, c = idx % 66, h = h0 + c - 1;
        sm[i][c] = (h >= 0 && h < HH) ? k[((size_t)b * NN + nin0 + i) * HH + h] : 0.f;
    }
    __syncthreads();
    __half* dst = g_kt + ((size_t)b * HH + h0) * OO + 3 * nin0;
    for (int idx = tid; idx < 64 * 96; idx += 256) {
        int j = idx / 96, p = idx % 96;
        int c0 = 2 * p, c1 = c0 + 1;
        int i0 = c0 / 3, d0 = c0 - 3 * i0;
        int i1 = c1 / 3, d1 = c1 - 3 * i1;
        *(__half2*)(dst + (size_t)j * OO + c0) =
            __floats2half2_rn(sm[i0][j + d0], sm[i1][j + d1]);
    }
}

// LayerNorm over H per (b,n) row
__global__ void __launch_bounds__(256)
ln_kernel(const float* __restrict__ gamma, const float* __restrict__ beta,
          float* __restrict__ out) {
    const int row = blockIdx.x, tid = threadIdx.x;
    const float* x = g_pre + (size_t)row * HH;
    float4 v = *(const float4*)(x + tid * 4);
    float s = v.x + v.y + v.z + v.w;
    float q = v.x * v.x + v.y * v.y + v.z * v.z + v.w * v.w;
#pragma unroll
    for (int o = 16; o; o >>= 1) {
        s += __shfl_xor_sync(0xFFFFFFFFu, s, o);
        q += __shfl_xor_sync(0xFFFFFFFFu, q, o);
    }
    __shared__ float ss[8], sq[8], red[2];
    if ((tid & 31) == 0) { ss[tid >> 5] = s; sq[tid >> 5] = q; }
    __syncthreads();
    if (tid == 0) {
        float S = 0.f, Q = 0.f;
#pragma unroll
        for (int i = 0; i < 8; i++) { S += ss[i]; Q += sq[i]; }
        float mu = S * (1.0f / HH);
        float var = Q * (1.0f / HH) - mu * mu;
        red[0] = mu;
        red[1] = rsqrtf(var + 1e-5f);
    }
    __syncthreads();
    const float mu = red[0], rinv = red[1];
    const int h = tid * 4;
    float4 g = *(const float4*)(gamma + h);
    float4 bt = *(const float4*)(beta + h);
    float4 y;
    y.x = (v.x - mu) * rinv * g.x + bt.x;
    y.y = (v.y - mu) * rinv * g.y + bt.y;
    y.z = (v.z - mu) * rinv * g.z + bt.z;
    y.w = (v.w - mu) * rinv * g.w + bt.w;
    *(float4*)(out + (size_t)row * HH + h) = y;
}

extern "C" void kernel_launch(void* const* d_in, const int* in_sizes, int n_in,
                              void* d_out, int out_size) {
    const float* f  = (const float*)d_in[0];
    const float* k  = (const float*)d_in[1];
    const float* W  = (const float*)d_in[2];
    const float* bl = (const float*)d_in[3];
    const float* gm = (const float*)d_in[4];
    const float* bt = (const float*)d_in[5];
    float* out = (float*)d_out;

    __half *f16p, *W16p;
    cudaGetSymbolAddress((void**)&f16p, g_f16);
    cudaGetSymbolAddress((void**)&W16p, g_W16);

    cudaFuncSetAttribute(gemm1_kernel, cudaFuncAttributeMaxDynamicSharedMemorySize, SMEM_TOTAL);
    cudaFuncSetAttribute(gemm2_kernel, cudaFuncAttributeMaxDynamicSharedMemorySize, SMEM_TOTAL);

    const int nf4 = BB * NN * HH / 4, nw4 = OO * HH / 4;
    cvt_kernel<<<(nf4 + 255) / 256, 256>>>(f, f16p, nf4);
    cvt_kernel<<<(nw4 + 255) / 256, 256>>>(W, W16p, nw4);
    ktbuild_kernel<<<dim3(4, 16, BB), 256>>>(k);

    gemm1_kernel<<<dim3(OO / 128, NN / 128, BB), 256, SMEM_TOTAL>>>(bl);
    gemm2_kernel<<<dim3(HH / 128, NN / 128, BB), 256, SMEM_TOTAL>>>();
    ln_kernel<<<BB * NN, 256>>>(gm, bt, out);
}

// round 15
// speedup vs baseline: 1.7417x; 1.1441x over previous
#include <cuda_runtime.h>
#include <cuda_fp16.h>
#include <cstdint>

#define DI __device__ __forceinline__

static constexpr int BB = 64, NN = 256, HH = 1024, OO = 768;
static constexpr int NI = 256;  // nin dim

// ---- static device scratch (no allocs allowed) ----
__device__ __align__(256) __half g_f16[(size_t)BB * NN * HH];    // fp16(f)
__device__ __align__(256) __half g_W16[(size_t)OO * HH];         // fp16(W_lin)
__device__ __align__(256) __half g_ktr[(size_t)BB * HH * NI];    // fp16 k transposed [b][h][nin]
__device__ __align__(256) __half g_wp[(size_t)3 * BB * NN * NI]; // w planes [d][b][n][nin]
__device__ __align__(256) float  g_pre[(size_t)BB * NN * HH];    // pre-LN [b][n][h]

// ---- helpers ----
DI uint32_t s2u(const void* p) {
    uint32_t a;
    asm("{ .reg .u64 t; cvta.to.shared.u64 t, %1; cvt.u32.u64 %0, t; }" : "=r"(a) : "l"(p));
    return a;
}
DI void ldx4(uint32_t r[4], uint32_t addr) {
    asm volatile("ldmatrix.sync.aligned.m8n8.x4.shared.b16 {%0,%1,%2,%3}, [%4];"
        : "=r"(r[0]), "=r"(r[1]), "=r"(r[2]), "=r"(r[3]) : "r"(addr));
}
DI void mma16816(float c[4], const uint32_t a[4], const uint32_t b[2]) {
    asm volatile("mma.sync.aligned.m16n8k16.row.col.f32.f16.f16.f32 "
        "{%0,%1,%2,%3}, {%4,%5,%6,%7}, {%8,%9}, {%0,%1,%2,%3};"
        : "+f"(c[0]), "+f"(c[1]), "+f"(c[2]), "+f"(c[3])
        : "r"(a[0]), "r"(a[1]), "r"(a[2]), "r"(a[3]), "r"(b[0]), "r"(b[1]));
}

static constexpr int STG = 32768;
static constexpr int SMEM_TOTAL = 66048;  // 2 stages (64K) < transpose reuse 66048

// LDG a fp16 128x64 tile into 4 uint4 regs
DI void ldg_tile(uint4 r[4], const __half* __restrict__ g, int lda, int tid) {
#pragma unroll
    for (int i = 0; i < 4; i++) {
        int q = tid + 256 * i, row = q >> 3, ck = q & 7;
        r[i] = *(const uint4*)(g + (size_t)row * lda + ck * 8);
    }
}
// Guarded variant: tile row r maps to global h = h0d + r; zero outside [0,HH)
DI void ldg_tile_g(uint4 r[4], const __half* __restrict__ g, int lda, int tid, int h0d) {
#pragma unroll
    for (int i = 0; i < 4; i++) {
        int q = tid + 256 * i, row = q >> 3, ck = q & 7;
        if ((unsigned)(h0d + row) < (unsigned)HH)
            r[i] = *(const uint4*)(g + (long long)row * lda + ck * 8);
        else
            r[i] = make_uint4(0u, 0u, 0u, 0u);
    }
}
// STS regs into swizzled smem tile
DI void sts_tile(const uint4 r[4], char* D, int tid) {
#pragma unroll
    for (int i = 0; i < 4; i++) {
        int q = tid + 256 * i, row = q >> 3, ck = q & 7;
        int off = row * 128 + ((ck ^ (row & 7)) << 4);
        *(uint4*)(D + off) = r[i];
    }
}

// One 64-wide K stage: acc += A.B
DI void compute_stage1(uint32_t smb, int buf, int wr, int wc, int lane, float acc[4][4][4]) {
    uint32_t Ah = smb + buf * STG;
    uint32_t Bh = Ah + 16384;
    const int ar = wr * 64 + (lane & 15);
    const int br = wc * 32 + (lane & 7) + ((lane & 16) >> 1);
    const int ax = lane & 7;
#pragma unroll
    for (int kk = 0; kk < 4; kk++) {
        const int ac = kk * 2 + (lane >> 4);
        const int bc = kk * 2 + ((lane >> 3) & 1);
        uint32_t ah[4][4], bh[4][2];
#pragma unroll
        for (int mt = 0; mt < 4; mt++)
            ldx4(ah[mt], Ah + (uint32_t)(ar + mt * 16) * 128 + (uint32_t)((ac ^ ax) << 4));
#pragma unroll
        for (int p = 0; p < 2; p++) {
            uint32_t off = (uint32_t)(br + p * 16) * 128 + (uint32_t)((bc ^ ax) << 4);
            uint32_t q[4];
            ldx4(q, Bh + off);
            bh[2 * p][0] = q[0]; bh[2 * p][1] = q[1];
            bh[2 * p + 1][0] = q[2]; bh[2 * p + 1][1] = q[3];
        }
#pragma unroll
        for (int mt = 0; mt < 4; mt++)
#pragma unroll
            for (int nt = 0; nt < 4; nt++) mma16816(acc[mt][nt], ah[mt], bh[nt]);
    }
}

// acc -> padded smem transpose
DI void epilogue_to_smem(float* eps, int wr, int wc, int lane, float acc[4][4][4]) {
#pragma unroll
    for (int mt = 0; mt < 4; mt++)
#pragma unroll
        for (int nt = 0; nt < 4; nt++) {
            int m = wr * 64 + mt * 16 + (lane >> 2);
            int n = wc * 32 + nt * 8 + (lane & 3) * 2;
            eps[m * 129 + n]           = acc[mt][nt][0];
            eps[m * 129 + n + 1]       = acc[mt][nt][1];
            eps[(m + 8) * 129 + n]     = acc[mt][nt][2];
            eps[(m + 8) * 129 + n + 1] = acc[mt][nt][3];
        }
}

// ===== GEMM1: wp[d][b][n][nin] = f16[b,n,:].W16[o=3nin+d,:] + b_lin[o] =====
__global__ void __launch_bounds__(256, 2)
gemm1_kernel(const float* __restrict__ bias) {
    extern __shared__ char sm[];
    uint32_t smb = s2u(sm);
    const int m0 = blockIdx.x * 128, n0 = blockIdx.y * 128, b = blockIdx.z;
    const int tid = threadIdx.x, w = tid >> 5, lane = tid & 31;
    const int wr = w >> 2, wc = w & 3;
    const __half* A = g_W16 + (size_t)m0 * HH;
    const __half* B = g_f16 + ((size_t)b * NN + n0) * HH;

    float acc[4][4][4];
#pragma unroll
    for (int i = 0; i < 4; i++)
#pragma unroll
        for (int j = 0; j < 4; j++)
#pragma unroll
            for (int c = 0; c < 4; c++) acc[i][j][c] = 0.f;

    uint4 ra[4], rb[4];
    ldg_tile(ra, A, HH, tid);
    ldg_tile(rb, B, HH, tid);
    sts_tile(ra, sm, tid);
    sts_tile(rb, sm + 16384, tid);
    __syncthreads();
    const int NS = HH / 64;  // 16
    for (int s = 0; s < NS; s++) {
        if (s + 1 < NS) {
            ldg_tile(ra, A + (s + 1) * 64, HH, tid);
            ldg_tile(rb, B + (s + 1) * 64, HH, tid);
        }
        compute_stage1(smb, s & 1, wr, wc, lane, acc);
        if (s + 1 < NS) {
            char* nb = sm + ((s + 1) & 1) * STG;
            sts_tile(ra, nb, tid);
            sts_tile(rb, nb + 16384, tid);
        }
        __syncthreads();
    }

    float* eps = (float*)sm;
    epilogue_to_smem(eps, wr, wc, lane, acc);
    __syncthreads();

    const int m = tid & 127, nh = (tid >> 7) * 64;
    const int o = m0 + m, d = o % 3, nin = o / 3;
    const float bv = bias[o];
    __half* oh = g_wp + (((size_t)d * BB + b) * NN + n0) * NI + nin;
#pragma unroll 8
    for (int j = 0; j < 64; j++) {
        int n = nh + j;
        oh[(size_t)n * NI] = __float2half_rn(eps[m * 129 + n] + bv);
    }
}

// ===== GEMM2: pre[b][n][h] = sum_{d,nin} ktr[b][h+d-1][nin] * wp[d][b][n][nin] =====
__global__ void __launch_bounds__(256, 2)
gemm2_kernel() {
    extern __shared__ char sm[];
    uint32_t smb = s2u(sm);
    const int h0 = blockIdx.x * 128, n0 = blockIdx.y * 128, b = blockIdx.z;
    const int tid = threadIdx.x, w = tid >> 5, lane = tid & 31;
    const int wr = w >> 2, wc = w & 3;
    const __half* ktr_b = g_ktr + (size_t)b * HH * NI;

    float acc[4][4][4];
#pragma unroll
    for (int i = 0; i < 4; i++)
#pragma unroll
        for (int j = 0; j < 4; j++)
#pragma unroll
            for (int c = 0; c < 4; c++) acc[i][j][c] = 0.f;

    uint4 ra[4], rb[4];
    // stage s: d = s>>2, c = s&3; A window rows h0+d-1.., B plane d chunk c
    ldg_tile_g(ra, ktr_b + (long long)(h0 - 1) * NI, NI, tid, h0 - 1);
    ldg_tile(rb, g_wp + ((size_t)b * NN + n0) * NI, NI, tid);
    sts_tile(ra, sm, tid);
    sts_tile(rb, sm + 16384, tid);
    __syncthreads();
    const int NS = 12;
    for (int s = 0; s < NS; s++) {
        if (s + 1 < NS) {
            int dn = (s + 1) >> 2, cn = (s + 1) & 3;
            ldg_tile_g(ra, ktr_b + (long long)(h0 + dn - 1) * NI + cn * 64, NI, tid, h0 + dn - 1);
            ldg_tile(rb, g_wp + (((size_t)dn * BB + b) * NN + n0) * NI + cn * 64, NI, tid);
        }
        compute_stage1(smb, s & 1, wr, wc, lane, acc);
        if (s + 1 < NS) {
            char* nb = sm + ((s + 1) & 1) * STG;
            sts_tile(ra, nb, tid);
            sts_tile(rb, nb + 16384, tid);
        }
        __syncthreads();
    }

    float* eps = (float*)sm;
    epilogue_to_smem(eps, wr, wc, lane, acc);
    __syncthreads();

    const int m = tid & 127, nh = (tid >> 7) * 64;
    float* ob = g_pre + ((size_t)b * NN + n0) * HH + h0 + m;
#pragma unroll 8
    for (int j = 0; j < 64; j++) {
        int n = nh + j;
        ob[(size_t)n * HH] = eps[m * 129 + n];
    }
}

// fp32 -> fp16 streaming convert
__global__ void __launch_bounds__(256)
cvt_kernel(const float* __restrict__ src, __half* __restrict__ dst, int n4) {
    int i = blockIdx.x * 256 + threadIdx.x;
    if (i < n4) {
        float4 v = ((const float4*)src)[i];
        ((__half2*)dst)[2 * i]     = __floats2half2_rn(v.x, v.y);
        ((__half2*)dst)[2 * i + 1] = __floats2half2_rn(v.z, v.w);
    }
}

// ktr[b][h][nin] = fp16(k[b][nin][h]) — tiled transpose
__global__ void __launch_bounds__(256)
ktr_kernel(const float* __restrict__ k) {
    __shared__ float t[64][65];
    const int b = blockIdx.z, nin0 = blockIdx.x * 64, h0 = blockIdx.y * 64;
    const int tid = threadIdx.x;
    {
        int i = tid >> 6, j = tid & 63;  // i: nin row (4 per pass), j: h col
#pragma unroll
        for (int r = 0; r < 16; r++)
            t[i + r * 4][j] = k[((size_t)b * NN + nin0 + i + r * 4) * HH + h0 + j];
    }
    __syncthreads();
    {
        int j = tid >> 5, i2 = (tid & 31) * 2;  // j: h (8 per pass), i2: nin pair
#pragma unroll
        for (int r = 0; r < 8; r++) {
            int jj = j + r * 8;
            __half2 v = __floats2half2_rn(t[i2][jj], t[i2 + 1][jj]);
            *(__half2*)(g_ktr + ((size_t)b * HH + h0 + jj) * NI + nin0 + i2) = v;
        }
    }
}

// LayerNorm over H per (b,n) row
__global__ void __launch_bounds__(256)
ln_kernel(const float* __restrict__ gamma, const float* __restrict__ beta,
          float* __restrict__ out) {
    const int row = blockIdx.x, tid = threadIdx.x;
    const float* x = g_pre + (size_t)row * HH;
    float4 v = *(const float4*)(x + tid * 4);
    float s = v.x + v.y + v.z + v.w;
    float q = v.x * v.x + v.y * v.y + v.z * v.z + v.w * v.w;
#pragma unroll
    for (int o = 16; o; o >>= 1) {
        s += __shfl_xor_sync(0xFFFFFFFFu, s, o);
        q += __shfl_xor_sync(0xFFFFFFFFu, q, o);
    }
    __shared__ float ss[8], sq[8], red[2];
    if ((tid & 31) == 0) { ss[tid >> 5] = s; sq[tid >> 5] = q; }
    __syncthreads();
    if (tid == 0) {
        float S = 0.f, Q = 0.f;
#pragma unroll
        for (int i = 0; i < 8; i++) { S += ss[i]; Q += sq[i]; }
        float mu = S * (1.0f / HH);
        float var = Q * (1.0f / HH) - mu * mu;
        red[0] = mu;
        red[1] = rsqrtf(var + 1e-5f);
    }
    __syncthreads();
    const float mu = red[0], rinv = red[1];
    const int h = tid * 4;
    float4 g = *(const float4*)(gamma + h);
    float4 bt = *(const float4*)(beta + h);
    float4 y;
    y.x = (v.x - mu) * rinv * g.x + bt.x;
    y.y = (v.y - mu) * rinv * g.y + bt.y;
    y.z = (v.z - mu) * rinv * g.z + bt.z;
    y.w = (v.w - mu) * rinv * g.w + bt.w;
    *(float4*)(out + (size_t)row * HH + h) = y;
}

extern "C" void kernel_launch(void* const* d_in, const int* in_sizes, int n_in,
                              void* d_out, int out_size) {
    const float* f  = (const float*)d_in[0];
    const float* k  = (const float*)d_in[1];
    const float* W  = (const float*)d_in[2];
    const float* bl = (const float*)d_in[3];
    const float* gm = (const float*)d_in[4];
    const float* bt = (const float*)d_in[5];
    float* out = (float*)d_out;

    __half *f16p, *W16p;
    cudaGetSymbolAddress((void**)&f16p, g_f16);
    cudaGetSymbolAddress((void**)&W16p, g_W16);

    cudaFuncSetAttribute(gemm1_kernel, cudaFuncAttributeMaxDynamicSharedMemorySize, SMEM_TOTAL);
    cudaFuncSetAttribute(gemm2_kernel, cudaFuncAttributeMaxDynamicSharedMemorySize, SMEM_TOTAL);

    const int nf4 = BB * NN * HH / 4, nw4 = OO * HH / 4;
    cvt_kernel<<<(nf4 + 255) / 256, 256>>>(f, f16p, nf4);
    cvt_kernel<<<(nw4 + 255) / 256, 256>>>(W, W16p, nw4);
    ktr_kernel<<<dim3(NN / 64, HH / 64, BB), 256>>>(k);

    gemm1_kernel<<<dim3(OO / 128, NN / 128, BB), 256, SMEM_TOTAL>>>(bl);
    gemm2_kernel<<<dim3(HH / 128, NN / 128, BB), 256, SMEM_TOTAL>>>();
    ln_kernel<<<BB * NN, 256>>>(gm, bt, out);
}